// round 13
// baseline (speedup 1.0000x reference)
#include <cuda_runtime.h>
#include <cstdint>

// Problem constants (fixed shapes per reference)
#define DIN    768
#define DSAE   16384
#define TDIM   12
#define KTOP   64
#define KBASIS 3
#define BSZ    1024
#define KDIM   9216

// GEMM tiling: CTA 128x128, 128 threads (4 warps, 2M x 2N, warp tile 64x64),
// 2 CTAs/SM. Split-K=2 -> grid (8,128,2) = 2048 CTAs.
#define KHALF    (KDIM / 2)       // 4608
#define KCH      32
#define NCHUNK   (KHALF / KCH)    // 144
#define NSTAGE   3
#define A_PITCH  36               // 36 mod 32 = 4 -> A frag hits all 32 banks
#define B_PITCH  136              // 136 mod 32 = 8 -> B frag conflict-free
#define A_ST_F   (128 * A_PITCH)  // 4608 floats
#define B_ST_F   (32 * B_PITCH)   // 4352 floats
#define STAGE_F  (A_ST_F + B_ST_F)         // 8960 floats
#define STAGE_B  (STAGE_F * 4)             // 35840 bytes
#define SMEM_B   (NSTAGE * STAGE_B)        // 107520 bytes (x2 CTAs = 215KB/SM)

// band half-width around approx 64th value (~40 sigma of tf32 RNA noise)
#define DELTA  0.03f
#define MAXB   64

// round fp32 bits to nearest tf32 (MMA truncates low 13 bits; +bit12 = RNA)
#define TF32RND(u) ((u) + 0x1000u)

// ---------------------------------------------------------------------------
// Device scratch
// ---------------------------------------------------------------------------
__device__ float g_pre [(size_t)BSZ * DSAE];     // 64 MB: K-half 0 partial
__device__ float g_pre2[(size_t)BSZ * DSAE];     // 64 MB: K-half 1 partial
__device__ int   g_idx[BSZ * KTOP];
__device__ float g_val[BSZ * KTOP];
__device__ int   g_scnt[BSZ];                    // certain count per row
__device__ int   g_bcnt[BSZ];                    // band count per row
__device__ int   g_bidx[BSZ][MAXB];              // band candidate indices
__device__ float g_bval[BSZ][MAXB];              // exact rescored values

// ---------------------------------------------------------------------------
// helpers
// ---------------------------------------------------------------------------
__device__ __forceinline__ uint32_t smem_u32(const void* p) {
    uint32_t a;
    asm("{ .reg .u64 t; cvta.to.shared.u64 t, %1; cvt.u32.u64 %0, t; }" : "=r"(a) : "l"(p));
    return a;
}

#define CP16(sa, ga) \
    asm volatile("cp.async.cg.shared.global [%0], [%1], 16;" :: "r"(sa), "l"(ga))
#define CP_COMMIT()  asm volatile("cp.async.commit_group;")
#define CP_WAIT1()   asm volatile("cp.async.wait_group 1;")
#define CP_WAIT0()   asm volatile("cp.async.wait_group 0;")

__device__ __forceinline__ void mma8(float* c, const uint32_t* a, const uint32_t* b) {
    asm volatile(
        "mma.sync.aligned.m16n8k8.row.col.f32.tf32.tf32.f32 "
        "{%0,%1,%2,%3}, {%4,%5,%6,%7}, {%8,%9}, {%0,%1,%2,%3};\n"
        : "+f"(c[0]), "+f"(c[1]), "+f"(c[2]), "+f"(c[3])
        : "r"(a[0]), "r"(a[1]), "r"(a[2]), "r"(a[3]), "r"(b[0]), "r"(b[1]));
}

// no-op kernel: pads launch index so ncu (-s 5) lands on topk this round.
// Index map: harness d_out poison=0, memset=1, nops=2..3, gemm=4, topk=5.
__global__ void nop_kernel() {}

// ---------------------------------------------------------------------------
// Kernel 1: single-pass tf32 mma.sync GEMM, cp.async producer, split-K=2,
// 2 CTAs/SM. NEW: fragment double-buffering — k-step ks+1's fragments load
// into the alternate register buffer while ks's 32 MMAs issue, breaking the
// LDS(29cyc)->MMA dependency wall seen as the 61% tensor plateau.
// ---------------------------------------------------------------------------
__global__ __launch_bounds__(128, 2)
void enc_gemm(const float* __restrict__ A,
              const float* __restrict__ B)
{
    extern __shared__ float sm[];
    const uint32_t sbase = smem_u32(sm);

    const int tid  = threadIdx.x;
    const int wid  = tid >> 5;
    const int lane = tid & 31;
    const int by   = blockIdx.x;   // M tile (0..7)   -- fast-varying for B reuse
    const int bx   = blockIdx.y;   // N tile (0..127)
    const int kz   = blockIdx.z;   // K half (0..1)

    const int wm = wid >> 1;       // 0..1  (64-row half)
    const int wn = wid & 1;        // 0..1  (64-col half)
    const int g  = lane >> 2;      // 0..7
    const int t  = lane & 3;       // 0..3

    const float* gA = A + (size_t)by * 128 * KDIM + (size_t)kz * KHALF;
    const float* gB = B + (size_t)kz * KHALF * DSAE + (size_t)bx * 128;
    float* gOut = (kz == 0 ? g_pre : g_pre2);

#define ISSUE(stage, c)                                                          \
    do {                                                                         \
        const uint32_t _sb = sbase + (uint32_t)(stage) * STAGE_B;                \
        const int _k0 = (c) * KCH;                                               \
        _Pragma("unroll")                                                        \
        for (int _i = 0; _i < 8; _i++) {                                         \
            const int _task = tid + _i * 128;                                    \
            const int _row = _task >> 3, _q = _task & 7;                         \
            CP16(_sb + (uint32_t)_row * (A_PITCH * 4) + (uint32_t)_q * 16,       \
                 gA + (size_t)_row * KDIM + _k0 + _q * 4);                       \
        }                                                                        \
        _Pragma("unroll")                                                        \
        for (int _i = 0; _i < 8; _i++) {                                         \
            const int _task = tid + _i * 128;                                    \
            const int _kr = _task >> 5, _cg = _task & 31;                        \
            CP16(_sb + (uint32_t)(A_ST_F * 4)                                    \
                     + (uint32_t)_kr * (B_PITCH * 4) + (uint32_t)_cg * 16,       \
                 gB + (size_t)(_k0 + _kr) * DSAE + _cg * 4);                     \
        }                                                                        \
        CP_COMMIT();                                                             \
    } while (0)

// load fragments for k-step `ks` into register buffer `buf`
#define LOADF(buf, ks)                                                           \
    do {                                                                         \
        _Pragma("unroll")                                                        \
        for (int _mt = 0; _mt < 4; _mt++) {                                      \
            const int _r0 = (wm * 64 + _mt * 16 + g) * A_PITCH + (ks) * 8 + t;   \
            Af[buf][_mt][0] = TF32RND(__float_as_uint(As[_r0]));                 \
            Af[buf][_mt][1] = TF32RND(__float_as_uint(As[_r0 + 8 * A_PITCH]));   \
            Af[buf][_mt][2] = TF32RND(__float_as_uint(As[_r0 + 4]));             \
            Af[buf][_mt][3] = TF32RND(__float_as_uint(As[_r0 + 8 * A_PITCH + 4]));\
        }                                                                        \
        _Pragma("unroll")                                                        \
        for (int _nt = 0; _nt < 8; _nt++) {                                      \
            const int _cb = ((ks) * 8 + t) * B_PITCH + wn * 64 + _nt * 8 + g;    \
            Bf[buf][_nt][0] = TF32RND(__float_as_uint(Bs[_cb]));                 \
            Bf[buf][_nt][1] = TF32RND(__float_as_uint(Bs[_cb + 4 * B_PITCH]));   \
        }                                                                        \
    } while (0)

    float acc[4][8][4];
#pragma unroll
    for (int mt = 0; mt < 4; mt++)
#pragma unroll
        for (int nt = 0; nt < 8; nt++)
#pragma unroll
            for (int q = 0; q < 4; q++) acc[mt][nt][q] = 0.f;

    ISSUE(0, 0);
    ISSUE(1, 1);

    int st = 0;
    for (int c = 0; c < NCHUNK; c++) {
        CP_WAIT1();
        __syncthreads();

        if (c + 2 < NCHUNK) {
            int ns = st + 2; if (ns >= NSTAGE) ns -= NSTAGE;
            ISSUE(ns, c + 2);
        }

        const float* As = sm + (size_t)st * STAGE_F;
        const float* Bs = As + A_ST_F;

        uint32_t Af[2][4][4], Bf[2][8][2];
        LOADF(0, 0);
#pragma unroll
        for (int ks = 0; ks < 4; ks++) {
            const int cur = ks & 1;
            if (ks < 3) {
                const int nxt = cur ^ 1;
                LOADF(nxt, ks + 1);
            }
#pragma unroll
            for (int mt = 0; mt < 4; mt++)
#pragma unroll
                for (int nt = 0; nt < 8; nt++)
                    mma8(acc[mt][nt], Af[cur][mt], Bf[cur][nt]);
        }

        if (++st >= NSTAGE) st = 0;
    }
    CP_WAIT0();

    // ---- epilogue: store raw partial (bias + half-sum folded into topk) ----
#pragma unroll
    for (int nt = 0; nt < 8; nt++) {
        const int col = bx * 128 + wn * 64 + nt * 8 + 2 * t;
#pragma unroll
        for (int mt = 0; mt < 4; mt++) {
            const size_t r0 = (size_t)(by * 128 + wm * 64 + mt * 16 + g) * DSAE + col;
            *(float2*)(gOut + r0) =
                make_float2(acc[mt][nt][0], acc[mt][nt][1]);
            *(float2*)(gOut + r0 + (size_t)8 * DSAE) =
                make_float2(acc[mt][nt][2], acc[mt][nt][3]);
        }
    }
}

// ---------------------------------------------------------------------------
// Kernel 2: per-row top-64 radix select on approx pre + certain/band split.
// pre = g_pre + g_pre2 + bias on load. NEW: warp-aggregated histogram
// (match_any) — one atomicAdd per distinct bin per warp instead of 32.
// ---------------------------------------------------------------------------
__device__ __forceinline__ unsigned f2k(float f) {
    unsigned u = __float_as_uint(f);
    return (u & 0x80000000u) ? ~u : (u | 0x80000000u);
}
__device__ __forceinline__ float k2f(unsigned k) {
    unsigned u = (k & 0x80000000u) ? (k & 0x7fffffffu) : ~k;
    return __uint_as_float(u);
}

__global__ void topk_kernel(float* __restrict__ z_out,
                            const float* __restrict__ bias)
{
    extern __shared__ unsigned skeys[];          // DSAE * 4 = 64 KB
    __shared__ unsigned hist[256];
    __shared__ int s_digit, s_take, s_cnt;

    const int b   = blockIdx.x;
    const int tid = threadIdx.x;
    const float* p0 = g_pre  + (size_t)b * DSAE;
    const float* p1 = g_pre2 + (size_t)b * DSAE;

    for (int e = tid; e < DSAE; e += 256)
        skeys[e] = f2k(p0[e] + p1[e] + bias[e]);
    if (tid == 0) { s_cnt = 0; g_bcnt[b] = 0; }
    __syncthreads();

    unsigned prefix = 0;
    int k_rem = KTOP;
#pragma unroll
    for (int r = 0; r < 4; r++) {
        const int shift = 24 - 8 * r;
        hist[tid] = 0;
        __syncthreads();
        for (int e = tid; e < DSAE; e += 256) {
            const unsigned key = skeys[e];
            if (r == 0 || (key >> (shift + 8)) == prefix) {
                const unsigned bin = (key >> shift) & 255u;
                // warp-aggregated histogram update
                const unsigned active = __activemask();
                const unsigned peers  = __match_any_sync(active, bin);
                const int leader = __ffs(peers) - 1;
                if ((int)(tid & 31) == leader)
                    atomicAdd(&hist[bin], (unsigned)__popc(peers));
            }
        }
        __syncthreads();
        if (tid == 0) {
            int c = 0, d;
            for (d = 255; d > 0; --d) {
                const int h = (int)hist[d];
                if (c + h >= k_rem) break;
                c += h;
            }
            s_digit = d;
            s_take  = k_rem - c;
        }
        __syncthreads();
        prefix = (prefix << 8) | (unsigned)s_digit;
        k_rem  = s_take;
        __syncthreads();
    }

    const float kv     = k2f(prefix);   // approx 64th-largest value
    const float hi_thr = kv + DELTA;
    const float lo_thr = kv - DELTA;

    for (int e = tid; e < DSAE; e += 256) {
        const float v = k2f(skeys[e]);
        if (v > hi_thr) {
            // certainly in exact top-64 (approx error << DELTA)
            const float zv = fmaxf(v, 0.f);
            z_out[(size_t)b * DSAE + e] = zv;
            const int p = atomicAdd(&s_cnt, 1);
            g_idx[b * KTOP + p] = e;
            g_val[b * KTOP + p] = zv;
        } else {
            z_out[(size_t)b * DSAE + e] = 0.f;   // band entries fixed up later
            if (v >= lo_thr) {
                const int q = atomicAdd(&g_bcnt[b], 1);
                if (q < MAXB) g_bidx[b][q] = e;
            }
        }
    }
    __syncthreads();
    if (tid == 0) g_scnt[b] = s_cnt;
}

// ---------------------------------------------------------------------------
// Kernel 3: exact rescoring of band candidates
// ---------------------------------------------------------------------------
__global__ __launch_bounds__(256)
void rescore_kernel(const float* __restrict__ x,
                    const float* __restrict__ W,
                    const float* __restrict__ bias)
{
    const int slot = blockIdx.x;
    const int b    = blockIdx.y;
    int cnt = g_bcnt[b];
    if (cnt > MAXB) cnt = MAXB;
    if (slot >= cnt) return;

    __shared__ float wsum[8];
    const int tid  = threadIdx.x;
    const int col  = g_bidx[b][slot];
    const float* xr = x + (size_t)b * KDIM;
    const float* wc = W + col;

    float s = 0.f;
#pragma unroll
    for (int i = 0; i < KDIM / 256; i++) {
        const int k = tid + i * 256;
        s = fmaf(xr[k], __ldg(&wc[(size_t)k * DSAE]), s);
    }
#pragma unroll
    for (int o = 16; o > 0; o >>= 1) s += __shfl_down_sync(0xffffffffu, s, o);
    if ((tid & 31) == 0) wsum[tid >> 5] = s;
    __syncthreads();
    if (tid == 0) {
        float tot = 0.f;
#pragma unroll
        for (int w = 0; w < 8; w++) tot += wsum[w];
        g_bval[b][slot] = tot + bias[col];
    }
}

// ---------------------------------------------------------------------------
// Kernel 4: fixup — rank band entries by exact score, fill remaining slots
// ---------------------------------------------------------------------------
__global__ __launch_bounds__(MAXB)
void fixup_kernel(float* __restrict__ z_out)
{
    __shared__ int   bi[MAXB];
    __shared__ float bv[MAXB];

    const int b   = blockIdx.x;
    const int tid = threadIdx.x;
    int cnt = g_bcnt[b];
    if (cnt > MAXB) cnt = MAXB;
    const int scnt = g_scnt[b];
    const int rem  = KTOP - scnt;

    if (tid < cnt) { bi[tid] = g_bidx[b][tid]; bv[tid] = g_bval[b][tid]; }
    __syncthreads();

    if (tid < cnt) {
        const int   mi = bi[tid];
        const float mv = bv[tid];
        int rank = 0;
        for (int j = 0; j < cnt; j++)
            rank += (bv[j] > mv) || (bv[j] == mv && bi[j] < mi);
        if (rank < rem) {
            const float zv = fmaxf(mv, 0.f);
            z_out[(size_t)b * DSAE + mi] = zv;
            const int pos = scnt + rank;
            g_idx[b * KTOP + pos] = mi;
            g_val[b * KTOP + pos] = zv;
        }
    }
}

// ---------------------------------------------------------------------------
// Kernel 5: sparse decode + basis combine + x_hat + loss
// ---------------------------------------------------------------------------
__global__ __launch_bounds__(256)
void decode_kernel(const float* __restrict__ x,
                   const float* __restrict__ Wb,
                   const float* __restrict__ alpha,
                   const float* __restrict__ b_dec,
                   float* __restrict__ xhat,
                   float* __restrict__ loss)
{
    __shared__ int   sidx[KTOP];
    __shared__ float sval[KTOP];
    __shared__ float salpha[TDIM * KBASIS];
    __shared__ float warpsum[8];

    const int b = blockIdx.x, tid = threadIdx.x;
    if (tid < KTOP)          { sidx[tid] = g_idx[b * KTOP + tid]; sval[tid] = g_val[b * KTOP + tid]; }
    if (tid < TDIM * KBASIS) { salpha[tid] = alpha[tid]; }
    __syncthreads();

    float acc[KBASIS][3];
#pragma unroll
    for (int k3 = 0; k3 < KBASIS; k3++)
#pragma unroll
        for (int dd = 0; dd < 3; dd++) acc[k3][dd] = 0.f;

    for (int j = 0; j < KTOP; j++) {
        const float v = sval[j];
        if (v == 0.f) continue;
        const int s = sidx[j];
        const float* wr = Wb + (size_t)s * DIN;
#pragma unroll
        for (int k3 = 0; k3 < KBASIS; k3++) {
            const float* w = wr + (size_t)k3 * DSAE * DIN;
#pragma unroll
            for (int dd = 0; dd < 3; dd++)
                acc[k3][dd] = fmaf(v, __ldg(&w[tid + dd * 256]), acc[k3][dd]);
        }
    }

    float lsum = 0.f;
#pragma unroll
    for (int t = 0; t < TDIM; t++) {
        const float a0 = salpha[t * KBASIS + 0];
        const float a1 = salpha[t * KBASIS + 1];
        const float a2 = salpha[t * KBASIS + 2];
#pragma unroll
        for (int dd = 0; dd < 3; dd++) {
            const int d = tid + dd * 256;
            const size_t off = ((size_t)b * TDIM + t) * DIN + d;
            const float xh = a0 * acc[0][dd] + a1 * acc[1][dd] + a2 * acc[2][dd]
                           + b_dec[t * DIN + d];
            xhat[off] = xh;
            const float diff = xh - x[off];
            lsum = fmaf(diff, diff, lsum);
        }
    }

#pragma unroll
    for (int o = 16; o > 0; o >>= 1) lsum += __shfl_down_sync(0xffffffffu, lsum, o);
    if ((tid & 31) == 0) warpsum[tid >> 5] = lsum;
    __syncthreads();
    if (tid == 0) {
        float s = 0.f;
#pragma unroll
        for (int w = 0; w < 8; w++) s += warpsum[w];
        atomicAdd(loss, s * (1.0f / (float)(BSZ * TDIM)));
    }
}

// ---------------------------------------------------------------------------
// kernel_launch: inputs = [x, W_enc, b_enc, W_base, alpha, b_dec, k]
// output (f32, concat): [recon_loss(1), x_hat(B*T*DIN), z(B*DSAE)]
// ---------------------------------------------------------------------------
extern "C" void kernel_launch(void* const* d_in, const int* in_sizes, int n_in,
                              void* d_out, int out_size)
{
    const float* x      = (const float*)d_in[0];
    const float* W_enc  = (const float*)d_in[1];
    const float* b_enc  = (const float*)d_in[2];
    const float* W_base = (const float*)d_in[3];
    const float* alpha  = (const float*)d_in[4];
    const float* b_dec  = (const float*)d_in[5];

    float* out  = (float*)d_out;
    float* loss = out;
    float* xhat = out + 1;
    float* z    = out + 1 + (size_t)BSZ * TDIM * DIN;

    cudaMemsetAsync(loss, 0, sizeof(float));

    // pad launch count: poison=0, memset=1, nops=2..3, gemm=4 -> topk at 5
    nop_kernel<<<1, 1>>>();
    nop_kernel<<<1, 1>>>();

    cudaFuncSetAttribute(enc_gemm,
                         cudaFuncAttributeMaxDynamicSharedMemorySize, SMEM_B);
    dim3 gemm_grid(BSZ / 128, DSAE / 128, 2);   // (8, 128, 2): split-K
    enc_gemm<<<gemm_grid, 128, SMEM_B>>>(x, W_enc);

    cudaFuncSetAttribute(topk_kernel,
                         cudaFuncAttributeMaxDynamicSharedMemorySize,
                         DSAE * (int)sizeof(unsigned));
    topk_kernel<<<BSZ, 256, DSAE * sizeof(unsigned)>>>(z, b_enc);

    rescore_kernel<<<dim3(MAXB, BSZ), 256>>>(x, W_enc, b_enc);
    fixup_kernel<<<BSZ, MAXB>>>(z);

    decode_kernel<<<BSZ, 256>>>(x, W_base, alpha, b_dec, xhat, loss);
}

// round 14
// speedup vs baseline: 1.1738x; 1.1738x over previous
#include <cuda_runtime.h>
#include <cstdint>

// Problem constants (fixed shapes per reference)
#define DIN    768
#define DSAE   16384
#define TDIM   12
#define KTOP   64
#define KBASIS 3
#define BSZ    1024
#define KDIM   9216

// GEMM tiling: CTA 128x128, 128 threads (4 warps, 2M x 2N, warp tile 64x64),
// 2 CTAs/SM. Split-K=2 -> grid (8,128,2) = 2048 CTAs.
#define KHALF    (KDIM / 2)       // 4608
#define KCH      32
#define NCHUNK   (KHALF / KCH)    // 144
#define NSTAGE   3
#define A_PITCH  36               // 36 mod 32 = 4 -> A frag hits all 32 banks
#define B_PITCH  136              // 136 mod 32 = 8 -> B frag conflict-free
#define A_ST_F   (128 * A_PITCH)  // 4608 floats
#define B_ST_F   (32 * B_PITCH)   // 4352 floats
#define STAGE_F  (A_ST_F + B_ST_F)         // 8960 floats
#define STAGE_B  (STAGE_F * 4)             // 35840 bytes
#define SMEM_B   (NSTAGE * STAGE_B)        // 107520 bytes (x2 CTAs = 215KB/SM)

// band half-width around approx 64th value. Noise sigma ~7e-4 (measured via
// rel_err 9.7e-5) -> 0.012 = 17 sigma. Shrinking 0.03 -> 0.012 cuts band
// count (and rescore's uncoalesced W-column traffic) ~3x.
#define DELTA  0.012f
#define MAXB   64

// round fp32 bits to nearest tf32 (MMA truncates low 13 bits; +bit12 = RNA)
#define TF32RND(u) ((u) + 0x1000u)

// ---------------------------------------------------------------------------
// Device scratch
// ---------------------------------------------------------------------------
__device__ float g_pre [(size_t)BSZ * DSAE];     // 64 MB: K-half 0 partial
__device__ float g_pre2[(size_t)BSZ * DSAE];     // 64 MB: K-half 1 partial
__device__ int   g_idx[BSZ * KTOP];
__device__ float g_val[BSZ * KTOP];
__device__ int   g_scnt[BSZ];                    // certain count per row
__device__ int   g_bcnt[BSZ];                    // band count per row
__device__ int   g_bidx[BSZ][MAXB];              // band candidate indices
__device__ float g_bval[BSZ][MAXB];              // exact rescored values

// ---------------------------------------------------------------------------
// helpers
// ---------------------------------------------------------------------------
__device__ __forceinline__ uint32_t smem_u32(const void* p) {
    uint32_t a;
    asm("{ .reg .u64 t; cvta.to.shared.u64 t, %1; cvt.u32.u64 %0, t; }" : "=r"(a) : "l"(p));
    return a;
}

#define CP16(sa, ga) \
    asm volatile("cp.async.cg.shared.global [%0], [%1], 16;" :: "r"(sa), "l"(ga))
#define CP_COMMIT()  asm volatile("cp.async.commit_group;")
#define CP_WAIT1()   asm volatile("cp.async.wait_group 1;")
#define CP_WAIT0()   asm volatile("cp.async.wait_group 0;")

__device__ __forceinline__ void mma8(float* c, const uint32_t* a, const uint32_t* b) {
    asm volatile(
        "mma.sync.aligned.m16n8k8.row.col.f32.tf32.tf32.f32 "
        "{%0,%1,%2,%3}, {%4,%5,%6,%7}, {%8,%9}, {%0,%1,%2,%3};\n"
        : "+f"(c[0]), "+f"(c[1]), "+f"(c[2]), "+f"(c[3])
        : "r"(a[0]), "r"(a[1]), "r"(a[2]), "r"(a[3]), "r"(b[0]), "r"(b[1]));
}

// no-op kernel: pads launch index so ncu (-s 5) lands on rescore this round.
// Index map: poison=0, memset=1, nop=2, gemm=3, topk=4, rescore=5.
__global__ void nop_kernel() {}

// ---------------------------------------------------------------------------
// Kernel 1: single-pass tf32 mma.sync GEMM (unchanged from R13 plateau).
// ---------------------------------------------------------------------------
__global__ __launch_bounds__(128, 2)
void enc_gemm(const float* __restrict__ A,
              const float* __restrict__ B)
{
    extern __shared__ float sm[];
    const uint32_t sbase = smem_u32(sm);

    const int tid  = threadIdx.x;
    const int wid  = tid >> 5;
    const int lane = tid & 31;
    const int by   = blockIdx.x;   // M tile (0..7)   -- fast-varying for B reuse
    const int bx   = blockIdx.y;   // N tile (0..127)
    const int kz   = blockIdx.z;   // K half (0..1)

    const int wm = wid >> 1;       // 0..1  (64-row half)
    const int wn = wid & 1;        // 0..1  (64-col half)
    const int g  = lane >> 2;      // 0..7
    const int t  = lane & 3;       // 0..3

    const float* gA = A + (size_t)by * 128 * KDIM + (size_t)kz * KHALF;
    const float* gB = B + (size_t)kz * KHALF * DSAE + (size_t)bx * 128;
    float* gOut = (kz == 0 ? g_pre : g_pre2);

#define ISSUE(stage, c)                                                          \
    do {                                                                         \
        const uint32_t _sb = sbase + (uint32_t)(stage) * STAGE_B;                \
        const int _k0 = (c) * KCH;                                               \
        _Pragma("unroll")                                                        \
        for (int _i = 0; _i < 8; _i++) {                                         \
            const int _task = tid + _i * 128;                                    \
            const int _row = _task >> 3, _q = _task & 7;                         \
            CP16(_sb + (uint32_t)_row * (A_PITCH * 4) + (uint32_t)_q * 16,       \
                 gA + (size_t)_row * KDIM + _k0 + _q * 4);                       \
        }                                                                        \
        _Pragma("unroll")                                                        \
        for (int _i = 0; _i < 8; _i++) {                                         \
            const int _task = tid + _i * 128;                                    \
            const int _kr = _task >> 5, _cg = _task & 31;                        \
            CP16(_sb + (uint32_t)(A_ST_F * 4)                                    \
                     + (uint32_t)_kr * (B_PITCH * 4) + (uint32_t)_cg * 16,       \
                 gB + (size_t)(_k0 + _kr) * DSAE + _cg * 4);                     \
        }                                                                        \
        CP_COMMIT();                                                             \
    } while (0)

#define LOADF(buf, ks)                                                           \
    do {                                                                         \
        _Pragma("unroll")                                                        \
        for (int _mt = 0; _mt < 4; _mt++) {                                      \
            const int _r0 = (wm * 64 + _mt * 16 + g) * A_PITCH + (ks) * 8 + t;   \
            Af[buf][_mt][0] = TF32RND(__float_as_uint(As[_r0]));                 \
            Af[buf][_mt][1] = TF32RND(__float_as_uint(As[_r0 + 8 * A_PITCH]));   \
            Af[buf][_mt][2] = TF32RND(__float_as_uint(As[_r0 + 4]));             \
            Af[buf][_mt][3] = TF32RND(__float_as_uint(As[_r0 + 8 * A_PITCH + 4]));\
        }                                                                        \
        _Pragma("unroll")                                                        \
        for (int _nt = 0; _nt < 8; _nt++) {                                      \
            const int _cb = ((ks) * 8 + t) * B_PITCH + wn * 64 + _nt * 8 + g;    \
            Bf[buf][_nt][0] = TF32RND(__float_as_uint(Bs[_cb]));                 \
            Bf[buf][_nt][1] = TF32RND(__float_as_uint(Bs[_cb + 4 * B_PITCH]));   \
        }                                                                        \
    } while (0)

    float acc[4][8][4];
#pragma unroll
    for (int mt = 0; mt < 4; mt++)
#pragma unroll
        for (int nt = 0; nt < 8; nt++)
#pragma unroll
            for (int q = 0; q < 4; q++) acc[mt][nt][q] = 0.f;

    ISSUE(0, 0);
    ISSUE(1, 1);

    int st = 0;
    for (int c = 0; c < NCHUNK; c++) {
        CP_WAIT1();
        __syncthreads();

        if (c + 2 < NCHUNK) {
            int ns = st + 2; if (ns >= NSTAGE) ns -= NSTAGE;
            ISSUE(ns, c + 2);
        }

        const float* As = sm + (size_t)st * STAGE_F;
        const float* Bs = As + A_ST_F;

        uint32_t Af[2][4][4], Bf[2][8][2];
        LOADF(0, 0);
#pragma unroll
        for (int ks = 0; ks < 4; ks++) {
            const int cur = ks & 1;
            if (ks < 3) {
                const int nxt = cur ^ 1;
                LOADF(nxt, ks + 1);
            }
#pragma unroll
            for (int mt = 0; mt < 4; mt++)
#pragma unroll
                for (int nt = 0; nt < 8; nt++)
                    mma8(acc[mt][nt], Af[cur][mt], Bf[cur][nt]);
        }

        if (++st >= NSTAGE) st = 0;
    }
    CP_WAIT0();

    // ---- epilogue: store raw partial (bias + half-sum folded into topk) ----
#pragma unroll
    for (int nt = 0; nt < 8; nt++) {
        const int col = bx * 128 + wn * 64 + nt * 8 + 2 * t;
#pragma unroll
        for (int mt = 0; mt < 4; mt++) {
            const size_t r0 = (size_t)(by * 128 + wm * 64 + mt * 16 + g) * DSAE + col;
            *(float2*)(gOut + r0) =
                make_float2(acc[mt][nt][0], acc[mt][nt][1]);
            *(float2*)(gOut + r0 + (size_t)8 * DSAE) =
                make_float2(acc[mt][nt][2], acc[mt][nt][3]);
        }
    }
}

// ---------------------------------------------------------------------------
// Kernel 2: per-row top-64 radix select (512 threads now: occ was 33.5%,
// latency-bound at 13% DRAM). pre = g_pre + g_pre2 + bias on load.
// ---------------------------------------------------------------------------
__device__ __forceinline__ unsigned f2k(float f) {
    unsigned u = __float_as_uint(f);
    return (u & 0x80000000u) ? ~u : (u | 0x80000000u);
}
__device__ __forceinline__ float k2f(unsigned k) {
    unsigned u = (k & 0x80000000u) ? (k & 0x7fffffffu) : ~k;
    return __uint_as_float(u);
}

__global__ __launch_bounds__(512)
void topk_kernel(float* __restrict__ z_out,
                 const float* __restrict__ bias)
{
    extern __shared__ unsigned skeys[];          // DSAE * 4 = 64 KB
    __shared__ unsigned hist[256];
    __shared__ int s_digit, s_take, s_cnt;

    const int b   = blockIdx.x;
    const int tid = threadIdx.x;
    const float* p0 = g_pre  + (size_t)b * DSAE;
    const float* p1 = g_pre2 + (size_t)b * DSAE;

    for (int e = tid; e < DSAE; e += 512)
        skeys[e] = f2k(p0[e] + p1[e] + bias[e]);
    if (tid == 0) { s_cnt = 0; g_bcnt[b] = 0; }
    __syncthreads();

    unsigned prefix = 0;
    int k_rem = KTOP;
#pragma unroll
    for (int r = 0; r < 4; r++) {
        const int shift = 24 - 8 * r;
        if (tid < 256) hist[tid] = 0;
        __syncthreads();
        for (int e = tid; e < DSAE; e += 512) {
            const unsigned key = skeys[e];
            if (r == 0 || (key >> (shift + 8)) == prefix) {
                const unsigned bin = (key >> shift) & 255u;
                const unsigned active = __activemask();
                const unsigned peers  = __match_any_sync(active, bin);
                const int leader = __ffs(peers) - 1;
                if ((int)(tid & 31) == leader)
                    atomicAdd(&hist[bin], (unsigned)__popc(peers));
            }
        }
        __syncthreads();
        if (tid == 0) {
            int c = 0, d;
            for (d = 255; d > 0; --d) {
                const int h = (int)hist[d];
                if (c + h >= k_rem) break;
                c += h;
            }
            s_digit = d;
            s_take  = k_rem - c;
        }
        __syncthreads();
        prefix = (prefix << 8) | (unsigned)s_digit;
        k_rem  = s_take;
        __syncthreads();
    }

    const float kv     = k2f(prefix);   // approx 64th-largest value
    const float hi_thr = kv + DELTA;
    const float lo_thr = kv - DELTA;

    for (int e = tid; e < DSAE; e += 512) {
        const float v = k2f(skeys[e]);
        if (v > hi_thr) {
            const float zv = fmaxf(v, 0.f);
            z_out[(size_t)b * DSAE + e] = zv;
            const int p = atomicAdd(&s_cnt, 1);
            g_idx[b * KTOP + p] = e;
            g_val[b * KTOP + p] = zv;
        } else {
            z_out[(size_t)b * DSAE + e] = 0.f;   // band entries fixed up later
            if (v >= lo_thr) {
                const int q = atomicAdd(&g_bcnt[b], 1);
                if (q < MAXB) g_bidx[b][q] = e;
            }
        }
    }
    __syncthreads();
    if (tid == 0) g_scnt[b] = s_cnt;
}

// ---------------------------------------------------------------------------
// Kernel 3: exact rescoring of band candidates
// ---------------------------------------------------------------------------
__global__ __launch_bounds__(256)
void rescore_kernel(const float* __restrict__ x,
                    const float* __restrict__ W,
                    const float* __restrict__ bias)
{
    const int slot = blockIdx.x;
    const int b    = blockIdx.y;
    int cnt = g_bcnt[b];
    if (cnt > MAXB) cnt = MAXB;
    if (slot >= cnt) return;

    __shared__ float wsum[8];
    const int tid  = threadIdx.x;
    const int col  = g_bidx[b][slot];
    const float* xr = x + (size_t)b * KDIM;
    const float* wc = W + col;

    float s = 0.f;
#pragma unroll
    for (int i = 0; i < KDIM / 256; i++) {
        const int k = tid + i * 256;
        s = fmaf(xr[k], __ldg(&wc[(size_t)k * DSAE]), s);
    }
#pragma unroll
    for (int o = 16; o > 0; o >>= 1) s += __shfl_down_sync(0xffffffffu, s, o);
    if ((tid & 31) == 0) wsum[tid >> 5] = s;
    __syncthreads();
    if (tid == 0) {
        float tot = 0.f;
#pragma unroll
        for (int w = 0; w < 8; w++) tot += wsum[w];
        g_bval[b][slot] = tot + bias[col];
    }
}

// ---------------------------------------------------------------------------
// Kernel 4: fixup — rank band entries by exact score, fill remaining slots
// ---------------------------------------------------------------------------
__global__ __launch_bounds__(MAXB)
void fixup_kernel(float* __restrict__ z_out)
{
    __shared__ int   bi[MAXB];
    __shared__ float bv[MAXB];

    const int b   = blockIdx.x;
    const int tid = threadIdx.x;
    int cnt = g_bcnt[b];
    if (cnt > MAXB) cnt = MAXB;
    const int scnt = g_scnt[b];
    const int rem  = KTOP - scnt;

    if (tid < cnt) { bi[tid] = g_bidx[b][tid]; bv[tid] = g_bval[b][tid]; }
    __syncthreads();

    if (tid < cnt) {
        const int   mi = bi[tid];
        const float mv = bv[tid];
        int rank = 0;
        for (int j = 0; j < cnt; j++)
            rank += (bv[j] > mv) || (bv[j] == mv && bi[j] < mi);
        if (rank < rem) {
            const float zv = fmaxf(mv, 0.f);
            z_out[(size_t)b * DSAE + mi] = zv;
            const int pos = scnt + rank;
            g_idx[b * KTOP + pos] = mi;
            g_val[b * KTOP + pos] = zv;
        }
    }
}

// ---------------------------------------------------------------------------
// Kernel 5: sparse decode + basis combine + x_hat + loss.
// grid (BSZ, 3): each block covers one 256-wide d-slice (3x parallelism for
// this latency-bound gather; traffic unchanged, still coalesced 1KB/warp-row).
// ---------------------------------------------------------------------------
__global__ __launch_bounds__(256)
void decode_kernel(const float* __restrict__ x,
                   const float* __restrict__ Wb,
                   const float* __restrict__ alpha,
                   const float* __restrict__ b_dec,
                   float* __restrict__ xhat,
                   float* __restrict__ loss)
{
    __shared__ int   sidx[KTOP];
    __shared__ float sval[KTOP];
    __shared__ float salpha[TDIM * KBASIS];
    __shared__ float warpsum[8];

    const int b = blockIdx.x, tid = threadIdx.x;
    const int d = blockIdx.y * 256 + tid;       // this block's d-slice
    if (tid < KTOP)          { sidx[tid] = g_idx[b * KTOP + tid]; sval[tid] = g_val[b * KTOP + tid]; }
    if (tid < TDIM * KBASIS) { salpha[tid] = alpha[tid]; }
    __syncthreads();

    float acc[KBASIS];
#pragma unroll
    for (int k3 = 0; k3 < KBASIS; k3++) acc[k3] = 0.f;

    for (int j = 0; j < KTOP; j++) {
        const float v = sval[j];
        if (v == 0.f) continue;
        const int s = sidx[j];
        const float* wr = Wb + (size_t)s * DIN + d;
#pragma unroll
        for (int k3 = 0; k3 < KBASIS; k3++)
            acc[k3] = fmaf(v, __ldg(&wr[(size_t)k3 * DSAE * DIN]), acc[k3]);
    }

    float lsum = 0.f;
#pragma unroll
    for (int t = 0; t < TDIM; t++) {
        const float a0 = salpha[t * KBASIS + 0];
        const float a1 = salpha[t * KBASIS + 1];
        const float a2 = salpha[t * KBASIS + 2];
        const size_t off = ((size_t)b * TDIM + t) * DIN + d;
        const float xh = a0 * acc[0] + a1 * acc[1] + a2 * acc[2]
                       + b_dec[t * DIN + d];
        xhat[off] = xh;
        const float diff = xh - x[off];
        lsum = fmaf(diff, diff, lsum);
    }

#pragma unroll
    for (int o = 16; o > 0; o >>= 1) lsum += __shfl_down_sync(0xffffffffu, lsum, o);
    if ((tid & 31) == 0) warpsum[tid >> 5] = lsum;
    __syncthreads();
    if (tid == 0) {
        float s = 0.f;
#pragma unroll
        for (int w = 0; w < 8; w++) s += warpsum[w];
        atomicAdd(loss, s * (1.0f / (float)(BSZ * TDIM)));
    }
}

// ---------------------------------------------------------------------------
// kernel_launch: inputs = [x, W_enc, b_enc, W_base, alpha, b_dec, k]
// output (f32, concat): [recon_loss(1), x_hat(B*T*DIN), z(B*DSAE)]
// ---------------------------------------------------------------------------
extern "C" void kernel_launch(void* const* d_in, const int* in_sizes, int n_in,
                              void* d_out, int out_size)
{
    const float* x      = (const float*)d_in[0];
    const float* W_enc  = (const float*)d_in[1];
    const float* b_enc  = (const float*)d_in[2];
    const float* W_base = (const float*)d_in[3];
    const float* alpha  = (const float*)d_in[4];
    const float* b_dec  = (const float*)d_in[5];

    float* out  = (float*)d_out;
    float* loss = out;
    float* xhat = out + 1;
    float* z    = out + 1 + (size_t)BSZ * TDIM * DIN;

    cudaMemsetAsync(loss, 0, sizeof(float));

    // pad launch count: poison=0, memset=1, nop=2, gemm=3, topk=4 -> rescore at 5
    nop_kernel<<<1, 1>>>();

    cudaFuncSetAttribute(enc_gemm,
                         cudaFuncAttributeMaxDynamicSharedMemorySize, SMEM_B);
    dim3 gemm_grid(BSZ / 128, DSAE / 128, 2);   // (8, 128, 2): split-K
    enc_gemm<<<gemm_grid, 128, SMEM_B>>>(x, W_enc);

    cudaFuncSetAttribute(topk_kernel,
                         cudaFuncAttributeMaxDynamicSharedMemorySize,
                         DSAE * (int)sizeof(unsigned));
    topk_kernel<<<BSZ, 512, DSAE * sizeof(unsigned)>>>(z, b_enc);

    rescore_kernel<<<dim3(MAXB, BSZ), 256>>>(x, W_enc, b_enc);
    fixup_kernel<<<BSZ, MAXB>>>(z);

    decode_kernel<<<dim3(BSZ, 3), 256>>>(x, W_base, alpha, b_dec, xhat, loss);
}

// round 15
// speedup vs baseline: 1.3024x; 1.1096x over previous
#include <cuda_runtime.h>
#include <cstdint>

// Problem constants (fixed shapes per reference)
#define DIN    768
#define DSAE   16384
#define TDIM   12
#define KTOP   64
#define KBASIS 3
#define BSZ    1024
#define KDIM   9216

// GEMM tiling: CTA 128x128, 128 threads (4 warps, 2M x 2N, warp tile 64x64),
// 2 CTAs/SM. Split-K=2 -> grid (8,128,2) = 2048 CTAs.
#define KHALF    (KDIM / 2)       // 4608
#define KCH      32
#define NCHUNK   (KHALF / KCH)    // 144
#define NSTAGE   3
#define A_PITCH  36               // 36 mod 32 = 4 -> A frag hits all 32 banks
#define B_PITCH  136              // 136 mod 32 = 8 -> B frag conflict-free
#define A_ST_F   (128 * A_PITCH)  // 4608 floats
#define B_ST_F   (32 * B_PITCH)   // 4352 floats
#define STAGE_F  (A_ST_F + B_ST_F)         // 8960 floats
#define STAGE_B  (STAGE_F * 4)             // 35840 bytes
#define SMEM_B   (NSTAGE * STAGE_B)        // 107520 bytes (x2 CTAs = 215KB/SM)

// band half-width (17 sigma of measured tf32 RNA noise sigma~7e-4)
#define DELTA  0.012f
#define MAXB   64

// rescore_stream config: 144 slabs x 64 k-rows = 9216
#define NSLAB      144
#define KSLAB      64
#define NC_PER_TH  24
#define NCAND_CAP  (NC_PER_TH * 256)   // 6144 (expected ~2300)
#define RS_SMEM    (2 * DSAE * 4)      // 128 KB double-buffered W rows

// round fp32 bits to nearest tf32 (MMA truncates low 13 bits; +bit12 = RNA)
#define TF32RND(u) ((u) + 0x1000u)

// ---------------------------------------------------------------------------
// Device scratch
// ---------------------------------------------------------------------------
__device__ float    g_pre [(size_t)BSZ * DSAE];  // 64 MB: K-half 0 partial
__device__ float    g_pre2[(size_t)BSZ * DSAE];  // 64 MB: K-half 1 partial
__device__ int      g_idx[BSZ * KTOP];
__device__ float    g_val[BSZ * KTOP];
__device__ int      g_scnt[BSZ];                 // certain count per row
__device__ int      g_bcnt[BSZ];                 // band count per row
__device__ int      g_bidx[BSZ][MAXB];           // band candidate indices
__device__ float    g_bval[BSZ][MAXB];           // exact rescored values (atomic)
__device__ unsigned g_ncand;                     // global candidate counter
__device__ unsigned g_cl[NCAND_CAP];             // packed (b<<20 | slot<<14 | col)

// ---------------------------------------------------------------------------
// helpers
// ---------------------------------------------------------------------------
__device__ __forceinline__ uint32_t smem_u32(const void* p) {
    uint32_t a;
    asm("{ .reg .u64 t; cvta.to.shared.u64 t, %1; cvt.u32.u64 %0, t; }" : "=r"(a) : "l"(p));
    return a;
}

#define CP16(sa, ga) \
    asm volatile("cp.async.cg.shared.global [%0], [%1], 16;" :: "r"(sa), "l"(ga))
#define CP_COMMIT()  asm volatile("cp.async.commit_group;")
#define CP_WAIT1()   asm volatile("cp.async.wait_group 1;")
#define CP_WAIT0()   asm volatile("cp.async.wait_group 0;")

__device__ __forceinline__ void mma8(float* c, const uint32_t* a, const uint32_t* b) {
    asm volatile(
        "mma.sync.aligned.m16n8k8.row.col.f32.tf32.tf32.f32 "
        "{%0,%1,%2,%3}, {%4,%5,%6,%7}, {%8,%9}, {%0,%1,%2,%3};\n"
        : "+f"(c[0]), "+f"(c[1]), "+f"(c[2]), "+f"(c[3])
        : "r"(a[0]), "r"(a[1]), "r"(a[2]), "r"(a[3]), "r"(b[0]), "r"(b[1]));
}

// ---------------------------------------------------------------------------
// Kernel 1: single-pass tf32 mma.sync GEMM (R13 plateau design, unchanged).
// ---------------------------------------------------------------------------
__global__ __launch_bounds__(128, 2)
void enc_gemm(const float* __restrict__ A,
              const float* __restrict__ B)
{
    extern __shared__ float sm[];
    const uint32_t sbase = smem_u32(sm);

    const int tid  = threadIdx.x;
    const int wid  = tid >> 5;
    const int lane = tid & 31;
    const int by   = blockIdx.x;
    const int bx   = blockIdx.y;
    const int kz   = blockIdx.z;

    const int wm = wid >> 1;
    const int wn = wid & 1;
    const int g  = lane >> 2;
    const int t  = lane & 3;

    const float* gA = A + (size_t)by * 128 * KDIM + (size_t)kz * KHALF;
    const float* gB = B + (size_t)kz * KHALF * DSAE + (size_t)bx * 128;
    float* gOut = (kz == 0 ? g_pre : g_pre2);

#define ISSUE(stage, c)                                                          \
    do {                                                                         \
        const uint32_t _sb = sbase + (uint32_t)(stage) * STAGE_B;                \
        const int _k0 = (c) * KCH;                                               \
        _Pragma("unroll")                                                        \
        for (int _i = 0; _i < 8; _i++) {                                         \
            const int _task = tid + _i * 128;                                    \
            const int _row = _task >> 3, _q = _task & 7;                         \
            CP16(_sb + (uint32_t)_row * (A_PITCH * 4) + (uint32_t)_q * 16,       \
                 gA + (size_t)_row * KDIM + _k0 + _q * 4);                       \
        }                                                                        \
        _Pragma("unroll")                                                        \
        for (int _i = 0; _i < 8; _i++) {                                         \
            const int _task = tid + _i * 128;                                    \
            const int _kr = _task >> 5, _cg = _task & 31;                        \
            CP16(_sb + (uint32_t)(A_ST_F * 4)                                    \
                     + (uint32_t)_kr * (B_PITCH * 4) + (uint32_t)_cg * 16,       \
                 gB + (size_t)(_k0 + _kr) * DSAE + _cg * 4);                     \
        }                                                                        \
        CP_COMMIT();                                                             \
    } while (0)

#define LOADF(buf, ks)                                                           \
    do {                                                                         \
        _Pragma("unroll")                                                        \
        for (int _mt = 0; _mt < 4; _mt++) {                                      \
            const int _r0 = (wm * 64 + _mt * 16 + g) * A_PITCH + (ks) * 8 + t;   \
            Af[buf][_mt][0] = TF32RND(__float_as_uint(As[_r0]));                 \
            Af[buf][_mt][1] = TF32RND(__float_as_uint(As[_r0 + 8 * A_PITCH]));   \
            Af[buf][_mt][2] = TF32RND(__float_as_uint(As[_r0 + 4]));             \
            Af[buf][_mt][3] = TF32RND(__float_as_uint(As[_r0 + 8 * A_PITCH + 4]));\
        }                                                                        \
        _Pragma("unroll")                                                        \
        for (int _nt = 0; _nt < 8; _nt++) {                                      \
            const int _cb = ((ks) * 8 + t) * B_PITCH + wn * 64 + _nt * 8 + g;    \
            Bf[buf][_nt][0] = TF32RND(__float_as_uint(Bs[_cb]));                 \
            Bf[buf][_nt][1] = TF32RND(__float_as_uint(Bs[_cb + 4 * B_PITCH]));   \
        }                                                                        \
    } while (0)

    float acc[4][8][4];
#pragma unroll
    for (int mt = 0; mt < 4; mt++)
#pragma unroll
        for (int nt = 0; nt < 8; nt++)
#pragma unroll
            for (int q = 0; q < 4; q++) acc[mt][nt][q] = 0.f;

    ISSUE(0, 0);
    ISSUE(1, 1);

    int st = 0;
    for (int c = 0; c < NCHUNK; c++) {
        CP_WAIT1();
        __syncthreads();

        if (c + 2 < NCHUNK) {
            int ns = st + 2; if (ns >= NSTAGE) ns -= NSTAGE;
            ISSUE(ns, c + 2);
        }

        const float* As = sm + (size_t)st * STAGE_F;
        const float* Bs = As + A_ST_F;

        uint32_t Af[2][4][4], Bf[2][8][2];
        LOADF(0, 0);
#pragma unroll
        for (int ks = 0; ks < 4; ks++) {
            const int cur = ks & 1;
            if (ks < 3) {
                const int nxt = cur ^ 1;
                LOADF(nxt, ks + 1);
            }
#pragma unroll
            for (int mt = 0; mt < 4; mt++)
#pragma unroll
                for (int nt = 0; nt < 8; nt++)
                    mma8(acc[mt][nt], Af[cur][mt], Bf[cur][nt]);
        }

        if (++st >= NSTAGE) st = 0;
    }
    CP_WAIT0();

#pragma unroll
    for (int nt = 0; nt < 8; nt++) {
        const int col = bx * 128 + wn * 64 + nt * 8 + 2 * t;
#pragma unroll
        for (int mt = 0; mt < 4; mt++) {
            const size_t r0 = (size_t)(by * 128 + wm * 64 + mt * 16 + g) * DSAE + col;
            *(float2*)(gOut + r0) =
                make_float2(acc[mt][nt][0], acc[mt][nt][1]);
            *(float2*)(gOut + r0 + (size_t)8 * DSAE) =
                make_float2(acc[mt][nt][2], acc[mt][nt][3]);
        }
    }
}

// ---------------------------------------------------------------------------
// Kernel 2: per-row top-64 radix select (512 thr). pre = p0+p1+bias on load.
// Also zeroes g_bval and pushes band candidates to the global compact list.
// ---------------------------------------------------------------------------
__device__ __forceinline__ unsigned f2k(float f) {
    unsigned u = __float_as_uint(f);
    return (u & 0x80000000u) ? ~u : (u | 0x80000000u);
}
__device__ __forceinline__ float k2f(unsigned k) {
    unsigned u = (k & 0x80000000u) ? (k & 0x7fffffffu) : ~k;
    return __uint_as_float(u);
}

__global__ __launch_bounds__(512)
void topk_kernel(float* __restrict__ z_out,
                 const float* __restrict__ bias)
{
    extern __shared__ unsigned skeys[];          // DSAE * 4 = 64 KB
    __shared__ unsigned hist[256];
    __shared__ int s_digit, s_take, s_cnt;

    const int b   = blockIdx.x;
    const int tid = threadIdx.x;
    const float* p0 = g_pre  + (size_t)b * DSAE;
    const float* p1 = g_pre2 + (size_t)b * DSAE;

    for (int e = tid; e < DSAE; e += 512)
        skeys[e] = f2k(p0[e] + p1[e] + bias[e]);
    if (tid == 0) { s_cnt = 0; g_bcnt[b] = 0; }
    if (tid < MAXB) g_bval[b][tid] = 0.f;        // slab partials accumulate here
    __syncthreads();

    unsigned prefix = 0;
    int k_rem = KTOP;
#pragma unroll
    for (int r = 0; r < 4; r++) {
        const int shift = 24 - 8 * r;
        if (tid < 256) hist[tid] = 0;
        __syncthreads();
        for (int e = tid; e < DSAE; e += 512) {
            const unsigned key = skeys[e];
            if (r == 0 || (key >> (shift + 8)) == prefix) {
                const unsigned bin = (key >> shift) & 255u;
                const unsigned active = __activemask();
                const unsigned peers  = __match_any_sync(active, bin);
                const int leader = __ffs(peers) - 1;
                if ((int)(tid & 31) == leader)
                    atomicAdd(&hist[bin], (unsigned)__popc(peers));
            }
        }
        __syncthreads();
        if (tid == 0) {
            int c = 0, d;
            for (d = 255; d > 0; --d) {
                const int h = (int)hist[d];
                if (c + h >= k_rem) break;
                c += h;
            }
            s_digit = d;
            s_take  = k_rem - c;
        }
        __syncthreads();
        prefix = (prefix << 8) | (unsigned)s_digit;
        k_rem  = s_take;
        __syncthreads();
    }

    const float kv     = k2f(prefix);   // approx 64th-largest value
    const float hi_thr = kv + DELTA;
    const float lo_thr = kv - DELTA;

    for (int e = tid; e < DSAE; e += 512) {
        const float v = k2f(skeys[e]);
        if (v > hi_thr) {
            const float zv = fmaxf(v, 0.f);
            z_out[(size_t)b * DSAE + e] = zv;
            const int p = atomicAdd(&s_cnt, 1);
            g_idx[b * KTOP + p] = e;
            g_val[b * KTOP + p] = zv;
        } else {
            z_out[(size_t)b * DSAE + e] = 0.f;   // band entries fixed up later
            if (v >= lo_thr) {
                const int q = atomicAdd(&g_bcnt[b], 1);
                if (q < MAXB) {
                    g_bidx[b][q] = e;
                    const unsigned gi = atomicAdd(&g_ncand, 1u);
                    if (gi < NCAND_CAP)
                        g_cl[gi] = ((unsigned)b << 20) | ((unsigned)q << 14)
                                 | (unsigned)e;
                }
            }
        }
    }
    __syncthreads();
    if (tid == 0) g_scnt[b] = s_cnt;
}

// ---------------------------------------------------------------------------
// Kernel 3: rescore_stream — exact band rescoring by streaming W once.
// 144 blocks, each owns a 64-row k-slab. W rows load coalesced (cp.async,
// double-buffered 2x64KB smem); each thread accumulates <=24 candidates'
// partial dots from smem; slab partials combine via atomicAdd into g_bval.
// Replaces the 2.4GB column-gather (12.5% sector efficiency) with a 576MB
// fully-coalesced stream.
// ---------------------------------------------------------------------------
__global__ __launch_bounds__(256)
void rescore_stream(const float* __restrict__ x,
                    const float* __restrict__ W)
{
    extern __shared__ float wrow[];   // 2 * DSAE floats
    const int tid  = threadIdx.x;
    const int k0   = blockIdx.x * KSLAB;

    int ncand = (int)g_ncand;
    if (ncand > NCAND_CAP) ncand = NCAND_CAP;

    uint32_t meta[NC_PER_TH];
    uint32_t xoff[NC_PER_TH];
    float    part[NC_PER_TH];
#pragma unroll
    for (int j = 0; j < NC_PER_TH; j++) {
        const int c = tid + j * 256;
        part[j] = 0.f;
        meta[j] = (c < ncand) ? g_cl[c] : 0xFFFFFFFFu;
        xoff[j] = (meta[j] >> 20) * (uint32_t)KDIM;
    }

    const uint32_t sbase = smem_u32(wrow);

    // prime buffer 0 with row k0
#pragma unroll
    for (int i = 0; i < 16; i++)
        CP16(sbase + (uint32_t)(tid + i * 256) * 16u,
             W + (size_t)k0 * DSAE + (size_t)(tid + i * 256) * 4);
    CP_COMMIT();

    for (int kk = 0; kk < KSLAB; kk++) {
        if (kk + 1 < KSLAB) {
            const uint32_t b2 = sbase + (uint32_t)((kk + 1) & 1) * (DSAE * 4u);
#pragma unroll
            for (int i = 0; i < 16; i++)
                CP16(b2 + (uint32_t)(tid + i * 256) * 16u,
                     W + (size_t)(k0 + kk + 1) * DSAE
                       + (size_t)(tid + i * 256) * 4);
            CP_COMMIT();
            CP_WAIT1();     // row kk complete (row kk+1 still in flight)
        } else {
            CP_WAIT0();
        }
        __syncthreads();

        const float* wr = wrow + (kk & 1) * DSAE;
        const uint32_t k = (uint32_t)(k0 + kk);
#pragma unroll
        for (int j = 0; j < NC_PER_TH; j++) {
            if (meta[j] != 0xFFFFFFFFu) {
                const float xv = __ldg(&x[(size_t)(xoff[j] + k)]);
                part[j] = fmaf(xv, wr[meta[j] & 0x3FFFu], part[j]);
            }
        }
        __syncthreads();    // all reads of this buffer done before reuse
    }

#pragma unroll
    for (int j = 0; j < NC_PER_TH; j++) {
        const uint32_t m = meta[j];
        if (m != 0xFFFFFFFFu) {
            const int bb = (int)(m >> 20);
            const int qq = (int)((m >> 14) & 63u);
            atomicAdd(&g_bval[bb][qq], part[j]);
        }
    }
}

// ---------------------------------------------------------------------------
// Kernel 4: fixup — rank band entries by exact score (+bias), fill slots
// ---------------------------------------------------------------------------
__global__ __launch_bounds__(MAXB)
void fixup_kernel(float* __restrict__ z_out,
                  const float* __restrict__ bias)
{
    __shared__ int   bi[MAXB];
    __shared__ float bv[MAXB];

    const int b   = blockIdx.x;
    const int tid = threadIdx.x;
    int cnt = g_bcnt[b];
    if (cnt > MAXB) cnt = MAXB;
    const int scnt = g_scnt[b];
    const int rem  = KTOP - scnt;

    if (tid < cnt) {
        bi[tid] = g_bidx[b][tid];
        bv[tid] = g_bval[b][tid] + bias[g_bidx[b][tid]];
    }
    __syncthreads();

    if (tid < cnt) {
        const int   mi = bi[tid];
        const float mv = bv[tid];
        int rank = 0;
        for (int j = 0; j < cnt; j++)
            rank += (bv[j] > mv) || (bv[j] == mv && bi[j] < mi);
        if (rank < rem) {
            const float zv = fmaxf(mv, 0.f);
            z_out[(size_t)b * DSAE + mi] = zv;
            const int pos = scnt + rank;
            g_idx[b * KTOP + pos] = mi;
            g_val[b * KTOP + pos] = zv;
        }
    }
}

// ---------------------------------------------------------------------------
// Kernel 5: sparse decode + basis combine + x_hat + loss. grid (BSZ, 3).
// ---------------------------------------------------------------------------
__global__ __launch_bounds__(256)
void decode_kernel(const float* __restrict__ x,
                   const float* __restrict__ Wb,
                   const float* __restrict__ alpha,
                   const float* __restrict__ b_dec,
                   float* __restrict__ xhat,
                   float* __restrict__ loss)
{
    __shared__ int   sidx[KTOP];
    __shared__ float sval[KTOP];
    __shared__ float salpha[TDIM * KBASIS];
    __shared__ float warpsum[8];

    const int b = blockIdx.x, tid = threadIdx.x;
    const int d = blockIdx.y * 256 + tid;
    if (tid < KTOP)          { sidx[tid] = g_idx[b * KTOP + tid]; sval[tid] = g_val[b * KTOP + tid]; }
    if (tid < TDIM * KBASIS) { salpha[tid] = alpha[tid]; }
    __syncthreads();

    float acc[KBASIS];
#pragma unroll
    for (int k3 = 0; k3 < KBASIS; k3++) acc[k3] = 0.f;

    for (int j = 0; j < KTOP; j++) {
        const float v = sval[j];
        if (v == 0.f) continue;
        const int s = sidx[j];
        const float* wr = Wb + (size_t)s * DIN + d;
#pragma unroll
        for (int k3 = 0; k3 < KBASIS; k3++)
            acc[k3] = fmaf(v, __ldg(&wr[(size_t)k3 * DSAE * DIN]), acc[k3]);
    }

    float lsum = 0.f;
#pragma unroll
    for (int t = 0; t < TDIM; t++) {
        const float a0 = salpha[t * KBASIS + 0];
        const float a1 = salpha[t * KBASIS + 1];
        const float a2 = salpha[t * KBASIS + 2];
        const size_t off = ((size_t)b * TDIM + t) * DIN + d;
        const float xh = a0 * acc[0] + a1 * acc[1] + a2 * acc[2]
                       + b_dec[t * DIN + d];
        xhat[off] = xh;
        const float diff = xh - x[off];
        lsum = fmaf(diff, diff, lsum);
    }

#pragma unroll
    for (int o = 16; o > 0; o >>= 1) lsum += __shfl_down_sync(0xffffffffu, lsum, o);
    if ((tid & 31) == 0) warpsum[tid >> 5] = lsum;
    __syncthreads();
    if (tid == 0) {
        float s = 0.f;
#pragma unroll
        for (int w = 0; w < 8; w++) s += warpsum[w];
        atomicAdd(loss, s * (1.0f / (float)(BSZ * TDIM)));
    }
}

// ---------------------------------------------------------------------------
// kernel_launch: inputs = [x, W_enc, b_enc, W_base, alpha, b_dec, k]
// output (f32, concat): [recon_loss(1), x_hat(B*T*DIN), z(B*DSAE)]
// ---------------------------------------------------------------------------
extern "C" void kernel_launch(void* const* d_in, const int* in_sizes, int n_in,
                              void* d_out, int out_size)
{
    const float* x      = (const float*)d_in[0];
    const float* W_enc  = (const float*)d_in[1];
    const float* b_enc  = (const float*)d_in[2];
    const float* W_base = (const float*)d_in[3];
    const float* alpha  = (const float*)d_in[4];
    const float* b_dec  = (const float*)d_in[5];

    float* out  = (float*)d_out;
    float* loss = out;
    float* xhat = out + 1;
    float* z    = out + 1 + (size_t)BSZ * TDIM * DIN;

    cudaMemsetAsync(loss, 0, sizeof(float));

    void* ncand_ptr = nullptr;
    cudaGetSymbolAddress(&ncand_ptr, g_ncand);
    cudaMemsetAsync(ncand_ptr, 0, sizeof(unsigned));

    // launch indices: poison=0, loss-memset=1, ncand-memset=2,
    //                 gemm=3, topk=4 -> rescore_stream profiled at 5

    cudaFuncSetAttribute(enc_gemm,
                         cudaFuncAttributeMaxDynamicSharedMemorySize, SMEM_B);
    dim3 gemm_grid(BSZ / 128, DSAE / 128, 2);   // (8, 128, 2): split-K
    enc_gemm<<<gemm_grid, 128, SMEM_B>>>(x, W_enc);

    cudaFuncSetAttribute(topk_kernel,
                         cudaFuncAttributeMaxDynamicSharedMemorySize,
                         DSAE * (int)sizeof(unsigned));
    topk_kernel<<<BSZ, 512, DSAE * sizeof(unsigned)>>>(z, b_enc);

    cudaFuncSetAttribute(rescore_stream,
                         cudaFuncAttributeMaxDynamicSharedMemorySize, RS_SMEM);
    rescore_stream<<<NSLAB, 256, RS_SMEM>>>(x, W_enc);

    fixup_kernel<<<BSZ, MAXB>>>(z, b_enc);

    decode_kernel<<<dim3(BSZ, 3), 256>>>(x, W_base, alpha, b_dec, xhat, loss);
}